// round 1
// baseline (speedup 1.0000x reference)
#include <cuda_runtime.h>
#include <math.h>

#define T_LEN 2048
#define B_SZ  64
#define I_SZ  256
#define H_SZ  256

// Recurrence partitioning: 16 batch-groups x 8 CTAs = 128 CTAs.
#define NGRP 16
#define CPG  8
#define NB   4     // batches per group
#define NC   32    // H columns per CTA

// ---------------- scratch (static device memory, no allocs) ----------------
__device__ float    g_xfh[(size_t)T_LEN * B_SZ * 512];   // [t][b][0:256]=xf, [256:512]=xh
__device__ float    g_hx[2][NGRP][NB][H_SZ];             // double-buffered h exchange
__device__ unsigned g_bar[NGRP][32];                     // padded barrier counters

// ---------------- init: reset barriers + zero h state ----------------------
__global__ void init_kernel() {
    int tid = blockIdx.x * blockDim.x + threadIdx.x;
    int n = 2 * NGRP * NB * H_SZ;
    float* p = &g_hx[0][0][0][0];
    for (int i = tid; i < n; i += blockDim.x * gridDim.x) p[i] = 0.0f;
    if (blockIdx.x == 0 && tid < NGRP) g_bar[tid][0] = 0u;
}

// ---------------- projection GEMM: C[131072,512] = seq @ [Wf|Wh] + [bf|bh] --
// 128x128 tile, BK=8, 256 threads, 8x8 per-thread microtile.
__global__ __launch_bounds__(256) void proj_kernel(
    const float* __restrict__ seq,
    const float* __restrict__ Wf, const float* __restrict__ bf,
    const float* __restrict__ Wh, const float* __restrict__ bh)
{
    __shared__ float As[8][132];
    __shared__ float Bs[8][132];

    const int bm = blockIdx.x;
    const int bn = blockIdx.y;                  // 0,1 -> Wf ; 2,3 -> Wh
    const float* __restrict__ W    = (bn < 2) ? Wf : Wh;
    const float* __restrict__ bias = (bn < 2) ? bf : bh;
    const int nb = (bn & 1) * 128;

    const int tid  = threadIdx.x;
    const int tx   = tid & 15;                  // n
    const int ty   = tid >> 4;                  // m
    const int arow = tid >> 1, acol = (tid & 1) * 4;
    const int brow = tid >> 5, bcol = (tid & 31) * 4;
    const size_t abase = (size_t)(bm * 128 + arow) * 256 + acol;

    float acc[8][8];
#pragma unroll
    for (int i = 0; i < 8; i++)
#pragma unroll
        for (int j = 0; j < 8; j++) acc[i][j] = 0.0f;

    for (int k0 = 0; k0 < 256; k0 += 8) {
        float4 av = *(const float4*)&seq[abase + k0];
        float4 bv = *(const float4*)&W[(size_t)(k0 + brow) * 256 + nb + bcol];
        __syncthreads();
        As[acol + 0][arow] = av.x;
        As[acol + 1][arow] = av.y;
        As[acol + 2][arow] = av.z;
        As[acol + 3][arow] = av.w;
        *(float4*)&Bs[brow][bcol] = bv;
        __syncthreads();
#pragma unroll
        for (int k = 0; k < 8; k++) {
            float ar[8], br[8];
            *(float4*)&ar[0] = *(const float4*)&As[k][ty * 8];
            *(float4*)&ar[4] = *(const float4*)&As[k][ty * 8 + 4];
            *(float4*)&br[0] = *(const float4*)&Bs[k][tx * 8];
            *(float4*)&br[4] = *(const float4*)&Bs[k][tx * 8 + 4];
#pragma unroll
            for (int i = 0; i < 8; i++)
#pragma unroll
                for (int j = 0; j < 8; j++)
                    acc[i][j] = fmaf(ar[i], br[j], acc[i][j]);
        }
    }

    float bb[8];
#pragma unroll
    for (int j = 0; j < 8; j++) bb[j] = bias[nb + tx * 8 + j];

#pragma unroll
    for (int i = 0; i < 8; i++) {
        size_t m = (size_t)bm * 128 + ty * 8 + i;
        float* op = &g_xfh[m * 512 + (size_t)bn * 128 + tx * 8];
#pragma unroll
        for (int j4 = 0; j4 < 8; j4 += 4) {
            float4 v;
            v.x = acc[i][j4 + 0] + bb[j4 + 0];
            v.y = acc[i][j4 + 1] + bb[j4 + 1];
            v.z = acc[i][j4 + 2] + bb[j4 + 2];
            v.w = acc[i][j4 + 3] + bb[j4 + 3];
            *(float4*)&op[j4] = v;
        }
    }
}

// ---------------- persistent recurrence kernel -----------------------------
// smem layout (dynamic): sU[2][NC][260] | sH[NB][260] | sRed[4][64] (float4)
#define SU_FLOATS  (2 * NC * 260)
#define SH_FLOATS  (NB * 260)
#define SRED_FLOATS (4 * 64 * 4)
#define REC_SMEM_BYTES ((SU_FLOATS + SH_FLOATS + SRED_FLOATS) * 4)

__global__ __launch_bounds__(256, 1) void rec_kernel(
    const float* __restrict__ Uf, const float* __restrict__ Uh,
    const float* __restrict__ pa, float* __restrict__ out)
{
    extern __shared__ float smem[];
    float (*sU)[NC][260] = (float (*)[NC][260])smem;
    float (*sH)[260]     = (float (*)[260])(smem + SU_FLOATS);
    float4* sRed         = (float4*)(smem + SU_FLOATS + SH_FLOATS);

    const int cta = blockIdx.x;
    const int g   = cta >> 3;       // batch group 0..15
    const int cgi = cta & 7;        // col-CTA within group
    const int j0  = cgi * NC;
    const int tid = threadIdx.x;

    // Load this CTA's U slices transposed: sU[mat][col][k] = U[k][j0+col]
    {
        int cc = tid & 31, k0 = tid >> 5;
        for (int kk = 0; kk < 32; kk++) {
            int k = kk * 8 + k0;
            sU[0][cc][k] = Uf[k * H_SZ + j0 + cc];
            sU[1][cc][k] = Uh[k * H_SZ + j0 + cc];
        }
    }
    const float aP = pa[0];

    const int jm  = tid & 63;       // (mat, col)
    const int ks  = tid >> 6;       // k-split 0..3
    const int col = jm & 31;
    const int mat = jm >> 5;
    const int kbase = ks * 64;
    const float* __restrict__ urow = &sU[mat][col][kbase];

    const int ecol = tid & 31;          // epilogue mapping (tid < 128)
    const int eb   = (tid >> 5) & 3;

    unsigned barTarget = 0;
    __syncthreads();

    for (int t = 0; t < T_LEN; t++) {
        const int slot = t & 1;

        // Load group's h slice (4x256 f32) from L2 (bypass L1: may be peer-written)
        {
            int b  = tid >> 6;
            int k4 = (tid & 63) << 2;
            float4 hv = __ldcg((const float4*)&g_hx[slot][g][b][k4]);
            *(float4*)&sH[b][k4] = hv;
        }

        // Prefetch xf/xh for epilogue (independent of h -> latency hidden)
        float xfv = 0.0f, xhv = 0.0f;
        if (tid < 128) {
            const int bglob = g * NB + eb;
            size_t base = ((size_t)t * B_SZ + bglob) * 512 + j0 + ecol;
            xfv = g_xfh[base];
            xhv = g_xfh[base + 256];
        }
        __syncthreads();

        // Partial dots: this thread covers (mat,col) x 4 batches over 64 k's
        float a0 = 0.f, a1 = 0.f, a2 = 0.f, a3 = 0.f;
#pragma unroll
        for (int k4 = 0; k4 < 64; k4 += 4) {
            float4 u  = *(const float4*)&urow[k4];
            float4 h0 = *(const float4*)&sH[0][kbase + k4];
            float4 h1 = *(const float4*)&sH[1][kbase + k4];
            float4 h2 = *(const float4*)&sH[2][kbase + k4];
            float4 h3 = *(const float4*)&sH[3][kbase + k4];
            a0 = fmaf(u.x, h0.x, a0); a0 = fmaf(u.y, h0.y, a0);
            a0 = fmaf(u.z, h0.z, a0); a0 = fmaf(u.w, h0.w, a0);
            a1 = fmaf(u.x, h1.x, a1); a1 = fmaf(u.y, h1.y, a1);
            a1 = fmaf(u.z, h1.z, a1); a1 = fmaf(u.w, h1.w, a1);
            a2 = fmaf(u.x, h2.x, a2); a2 = fmaf(u.y, h2.y, a2);
            a2 = fmaf(u.z, h2.z, a2); a2 = fmaf(u.w, h2.w, a2);
            a3 = fmaf(u.x, h3.x, a3); a3 = fmaf(u.y, h3.y, a3);
            a3 = fmaf(u.z, h3.z, a3); a3 = fmaf(u.w, h3.w, a3);
        }
        sRed[ks * 64 + jm] = make_float4(a0, a1, a2, a3);
        __syncthreads();

        // Epilogue: 128 threads, one (b, col) output each
        if (tid < 128) {
            const float* rf = (const float*)sRed;
            float pf = rf[(0 * 64 + ecol) * 4 + eb]
                     + rf[(1 * 64 + ecol) * 4 + eb]
                     + rf[(2 * 64 + ecol) * 4 + eb]
                     + rf[(3 * 64 + ecol) * 4 + eb] + xfv;
            float ph = rf[(0 * 64 + 32 + ecol) * 4 + eb]
                     + rf[(1 * 64 + 32 + ecol) * 4 + eb]
                     + rf[(2 * 64 + 32 + ecol) * 4 + eb]
                     + rf[(3 * 64 + 32 + ecol) * 4 + eb] + xhv;

            float f  = 1.0f / (1.0f + expf(-pf));
            float hn = tanhf(ph);
            float ho = sH[eb][j0 + ecol];
            float hv = f * ho + (1.0f - f) * hn;
            hv = (hv >= 0.0f) ? hv : aP * hv;

            const int bglob = g * NB + eb;
            out[((size_t)t * B_SZ + bglob) * H_SZ + j0 + ecol] = hv;
            __stcg(&g_hx[slot ^ 1][g][eb][j0 + ecol], hv);
        }

        // Group barrier (release: threadfence before arrive)
        __threadfence();
        __syncthreads();
        barTarget += CPG;
        if (tid == 0) {
            atomicAdd(&g_bar[g][0], 1u);
            while (atomicAdd(&g_bar[g][0], 0u) < barTarget) { }
        }
        __syncthreads();
    }
}

// ---------------- launch ----------------------------------------------------
extern "C" void kernel_launch(void* const* d_in, const int* in_sizes, int n_in,
                              void* d_out, int out_size) {
    (void)in_sizes; (void)n_in; (void)out_size;
    const float* seq = (const float*)d_in[0];
    const float* Wf  = (const float*)d_in[1];
    const float* Uf  = (const float*)d_in[2];
    const float* bf  = (const float*)d_in[3];
    const float* Wh  = (const float*)d_in[4];
    const float* Uh  = (const float*)d_in[5];
    const float* bh  = (const float*)d_in[6];
    const float* pa  = (const float*)d_in[7];
    float* out = (float*)d_out;

    init_kernel<<<64, 256>>>();

    dim3 pgrid(T_LEN * B_SZ / 128, 4);
    proj_kernel<<<pgrid, 256>>>(seq, Wf, bf, Wh, bh);

    cudaFuncSetAttribute(rec_kernel, cudaFuncAttributeMaxDynamicSharedMemorySize,
                         REC_SMEM_BYTES);
    rec_kernel<<<NGRP * CPG, 256, REC_SMEM_BYTES>>>(Uf, Uh, pa, out);
}

// round 2
// speedup vs baseline: 1.1334x; 1.1334x over previous
#include <cuda_runtime.h>
#include <math.h>

#define T_LEN 2048
#define B_SZ  64
#define I_SZ  256
#define H_SZ  256

// Recurrence partitioning: 16 batch-groups x 8 CTAs = 128 CTAs.
#define NGRP 16
#define CPG  8
#define NB   4     // batches per group
#define NC   32    // H output columns per CTA

typedef unsigned long long u64;

__device__ __forceinline__ void fma2(u64 &d, u64 a, u64 b) {
    asm("fma.rn.f32x2 %0, %1, %2, %0;" : "+l"(d) : "l"(a), "l"(b));
}
__device__ __forceinline__ float2 u2f(u64 v) {
    float2 r; asm("mov.b64 {%0, %1}, %2;" : "=f"(r.x), "=f"(r.y) : "l"(v)); return r;
}

// ---------------- scratch (static device memory, no allocs) ----------------
__device__ float    g_xfh[(size_t)T_LEN * B_SZ * 512];   // [t][b][0:256]=xf, [256:512]=xh
__device__ float    g_hx[2][NGRP][NB][H_SZ];             // double-buffered h exchange
__device__ unsigned g_bar[NGRP][32];                     // padded barrier counters

// ---------------- init: reset barriers + zero h state ----------------------
__global__ void init_kernel() {
    int tid = blockIdx.x * blockDim.x + threadIdx.x;
    int n = 2 * NGRP * NB * H_SZ;
    float* p = &g_hx[0][0][0][0];
    for (int i = tid; i < n; i += blockDim.x * gridDim.x) p[i] = 0.0f;
    if (blockIdx.x == 0 && tid < NGRP) g_bar[tid][0] = 0u;
}

// ---------------- projection GEMM: C[131072,512] = seq @ [Wf|Wh] + [bf|bh] --
// 128x128 tile, BK=8, 256 threads, 8x8 microtile on packed f32x2 FMA.
__global__ __launch_bounds__(256) void proj_kernel(
    const float* __restrict__ seq,
    const float* __restrict__ Wf, const float* __restrict__ bf,
    const float* __restrict__ Wh, const float* __restrict__ bh)
{
    __shared__ float2 As2[8][130];   // duplicated a: As2[k][m] = (a, a)
    __shared__ float  Bs[8][132];

    const int bm = blockIdx.x;
    const int bn = blockIdx.y;                  // 0,1 -> Wf ; 2,3 -> Wh
    const float* __restrict__ W    = (bn < 2) ? Wf : Wh;
    const float* __restrict__ bias = (bn < 2) ? bf : bh;
    const int nb = (bn & 1) * 128;

    const int tid  = threadIdx.x;
    const int tx   = tid & 15;                  // n
    const int ty   = tid >> 4;                  // m
    const int arow = tid >> 1, acol = (tid & 1) * 4;
    const int brow = tid >> 5, bcol = (tid & 31) * 4;
    const size_t abase = (size_t)(bm * 128 + arow) * 256 + acol;

    u64 acc[8][4];
#pragma unroll
    for (int i = 0; i < 8; i++)
#pragma unroll
        for (int j = 0; j < 4; j++) acc[i][j] = 0ull;

    for (int k0 = 0; k0 < 256; k0 += 8) {
        float4 av = *(const float4*)&seq[abase + k0];
        float4 bv = *(const float4*)&W[(size_t)(k0 + brow) * 256 + nb + bcol];
        __syncthreads();
        As2[acol + 0][arow] = make_float2(av.x, av.x);
        As2[acol + 1][arow] = make_float2(av.y, av.y);
        As2[acol + 2][arow] = make_float2(av.z, av.z);
        As2[acol + 3][arow] = make_float2(av.w, av.w);
        *(float4*)&Bs[brow][bcol] = bv;
        __syncthreads();
#pragma unroll
        for (int k = 0; k < 8; k++) {
            ulonglong2 a01 = *(const ulonglong2*)&As2[k][ty * 8 + 0];
            ulonglong2 a23 = *(const ulonglong2*)&As2[k][ty * 8 + 2];
            ulonglong2 a45 = *(const ulonglong2*)&As2[k][ty * 8 + 4];
            ulonglong2 a67 = *(const ulonglong2*)&As2[k][ty * 8 + 6];
            ulonglong2 b01 = *(const ulonglong2*)&Bs[k][tx * 8];      // (b0,b1),(b2,b3)
            ulonglong2 b23 = *(const ulonglong2*)&Bs[k][tx * 8 + 4];  // (b4,b5),(b6,b7)
            u64 ad[8] = {a01.x, a01.y, a23.x, a23.y, a45.x, a45.y, a67.x, a67.y};
#pragma unroll
            for (int i = 0; i < 8; i++) {
                fma2(acc[i][0], ad[i], b01.x);
                fma2(acc[i][1], ad[i], b01.y);
                fma2(acc[i][2], ad[i], b23.x);
                fma2(acc[i][3], ad[i], b23.y);
            }
        }
    }

    float bb[8];
#pragma unroll
    for (int j = 0; j < 8; j++) bb[j] = bias[nb + tx * 8 + j];

#pragma unroll
    for (int i = 0; i < 8; i++) {
        size_t m = (size_t)bm * 128 + ty * 8 + i;
        float* op = &g_xfh[m * 512 + (size_t)bn * 128 + tx * 8];
        float2 c0 = u2f(acc[i][0]), c1 = u2f(acc[i][1]);
        float2 c2 = u2f(acc[i][2]), c3 = u2f(acc[i][3]);
        float4 v0, v1;
        v0.x = c0.x + bb[0]; v0.y = c0.y + bb[1];
        v0.z = c1.x + bb[2]; v0.w = c1.y + bb[3];
        v1.x = c2.x + bb[4]; v1.y = c2.y + bb[5];
        v1.z = c3.x + bb[6]; v1.w = c3.y + bb[7];
        *(float4*)&op[0] = v0;
        *(float4*)&op[4] = v1;
    }
}

// ---------------- persistent recurrence kernel -----------------------------
// Warp w owns k-range [32w, 32w+32); lane owns virtual cols (2l, 2l+1)
// (vc<32 -> Uf col vc; vc>=32 -> Uh col vc-32). U lives in registers as
// natural (c0,c1) f32x2 pairs. h lives in smem duplicated: sH8[k] =
// (h0,h0,h1,h1,h2,h2,h3,h3) so FMA2 b-operands need no packing.
#define SH8_STRIDE 12   // floats per k row (8 used + 4 pad -> conflict-free)

__global__ __launch_bounds__(256, 1) void rec_kernel(
    const float* __restrict__ Uf, const float* __restrict__ Uh,
    const float* __restrict__ pa, float* __restrict__ out)
{
    __shared__ float sH8[256 * SH8_STRIDE];   // 12 KB
    __shared__ float sRed[64 * 33];           // 8.4 KB: [vc][b*8+w]

    const int cta = blockIdx.x;
    const int g   = cta >> 3;       // batch group 0..15
    const int cgi = cta & 7;        // col-CTA within group
    const int j0  = cgi * NC;
    const int tid = threadIdx.x;
    const int w   = tid >> 5;       // k-chunk
    const int l   = tid & 31;
    const int kb  = w * 32;
    const int vc0 = 2 * l;          // virtual col pair (vc0, vc0+1)

    // Load this thread's U slice into registers as packed (c0,c1) pairs.
    const float* __restrict__ Usrc = (vc0 < 32) ? Uf : Uh;
    const int colb = j0 + (vc0 & 31);
    u64 uu[32];
#pragma unroll
    for (int i = 0; i < 32; i++)
        uu[i] = *(const u64*)&Usrc[(size_t)(kb + i) * H_SZ + colb];

    const float aP = pa[0];
    const int ecol = tid & 31;      // epilogue mapping (tid < 128)
    const int eb   = tid >> 5;
    unsigned barTarget = 0;
    volatile unsigned* barp = &g_bar[g][0];
    (void)barp;

    for (int t = 0; t < T_LEN; t++) {
        const int slot = t & 1;

        // Fill own warp's k-range of sH8 (thread tid handles k = tid).
        {
            const float* hp = &g_hx[slot][g][0][0];
            float h0 = __ldcg(hp + 0 * H_SZ + tid);
            float h1 = __ldcg(hp + 1 * H_SZ + tid);
            float h2 = __ldcg(hp + 2 * H_SZ + tid);
            float h3 = __ldcg(hp + 3 * H_SZ + tid);
            float4* dst = (float4*)&sH8[tid * SH8_STRIDE];
            dst[0] = make_float4(h0, h0, h1, h1);
            dst[1] = make_float4(h2, h2, h3, h3);
        }
        // Prefetch xf/xh for epilogue (independent of h).
        float xfv = 0.0f, xhv = 0.0f;
        if (tid < 128) {
            size_t base = ((size_t)t * B_SZ + g * NB + eb) * 512 + j0 + ecol;
            xfv = g_xfh[base];
            xhv = g_xfh[base + 256];
        }
        __syncwarp();   // warp w reads only k filled by its own lanes

        u64 acc0 = 0ull, acc1 = 0ull, acc2v = 0ull, acc3 = 0ull;
#pragma unroll
        for (int i = 0; i < 32; i++) {
            const int k = kb + i;
            ulonglong2 hA = *(const ulonglong2*)&sH8[k * SH8_STRIDE];      // (h0,h0),(h1,h1)
            ulonglong2 hB = *(const ulonglong2*)&sH8[k * SH8_STRIDE + 4];  // (h2,h2),(h3,h3)
            fma2(acc0, uu[i], hA.x);
            fma2(acc1, uu[i], hA.y);
            fma2(acc2v, uu[i], hB.x);
            fma2(acc3, uu[i], hB.y);
        }
        {
            float2 p0 = u2f(acc0), p1 = u2f(acc1), p2 = u2f(acc2v), p3 = u2f(acc3);
            float* r0 = &sRed[vc0 * 33 + w];
            float* r1 = &sRed[(vc0 + 1) * 33 + w];
            r0[0] = p0.x;  r1[0] = p0.y;
            r0[8] = p1.x;  r1[8] = p1.y;
            r0[16] = p2.x; r1[16] = p2.y;
            r0[24] = p3.x; r1[24] = p3.y;
        }
        __syncthreads();

        // Epilogue: 128 threads, one (b, col) output each.
        if (tid < 128) {
            const float* rf = &sRed[ecol * 33 + eb * 8];
            const float* rh = &sRed[(ecol + 32) * 33 + eb * 8];
            float pf = ((rf[0] + rf[1]) + (rf[2] + rf[3]))
                     + ((rf[4] + rf[5]) + (rf[6] + rf[7])) + xfv;
            float ph = ((rh[0] + rh[1]) + (rh[2] + rh[3]))
                     + ((rh[4] + rh[5]) + (rh[6] + rh[7])) + xhv;

            float f  = 1.0f / (1.0f + expf(-pf));
            float hn = tanhf(ph);
            float ho = sH8[(j0 + ecol) * SH8_STRIDE + 2 * eb];
            float hv = f * ho + (1.0f - f) * hn;
            hv = (hv >= 0.0f) ? hv : aP * hv;

            out[((size_t)t * B_SZ + g * NB + eb) * H_SZ + j0 + ecol] = hv;
            __stcg(&g_hx[slot ^ 1][g][eb][j0 + ecol], hv);
        }
        __syncthreads();   // all h writes of this CTA done before arrive

        barTarget += CPG;
        if (tid == 0) {
            asm volatile("red.release.gpu.global.add.u32 [%0], 1;"
                         :: "l"(&g_bar[g][0]) : "memory");
            unsigned v;
            do {
                asm volatile("ld.acquire.gpu.global.u32 %0, [%1];"
                             : "=r"(v) : "l"(&g_bar[g][0]) : "memory");
            } while (v < barTarget);
        }
        __syncthreads();
    }
}

// ---------------- launch ----------------------------------------------------
extern "C" void kernel_launch(void* const* d_in, const int* in_sizes, int n_in,
                              void* d_out, int out_size) {
    (void)in_sizes; (void)n_in; (void)out_size;
    const float* seq = (const float*)d_in[0];
    const float* Wf  = (const float*)d_in[1];
    const float* Uf  = (const float*)d_in[2];
    const float* bf  = (const float*)d_in[3];
    const float* Wh  = (const float*)d_in[4];
    const float* Uh  = (const float*)d_in[5];
    const float* bh  = (const float*)d_in[6];
    const float* pa  = (const float*)d_in[7];
    float* out = (float*)d_out;

    init_kernel<<<64, 256>>>();

    dim3 pgrid(T_LEN * B_SZ / 128, 4);
    proj_kernel<<<pgrid, 256>>>(seq, Wf, bf, Wh, bh);

    rec_kernel<<<NGRP * CPG, 256>>>(Uf, Uh, pa, out);
}